// round 14
// baseline (speedup 1.0000x reference)
#include <cuda_runtime.h>
#include <cuda_fp16.h>
#include <cstdint>

// Problem shape (fixed)
#define BB   4
#define LL   4096
#define DD   1024
#define DFF_ 4096
#define MM   (BB*LL)        // 16384 token rows
#define NCH  128
#define CHUNK 32

// ---------------- scratch (device globals: allocation-free) ----------------
__device__ float  g_a  [MM*DD];     // sigmoid(forget)  (fp32: 1/(1-a) error amplification)
__device__ __half g_bvh[MM*DD];     // tanh(input)*sigmoid(igate)
__device__ __half g_oh [MM*DD];     // sigmoid(ogate)
__device__ float  g_x1 [MM*DD];
__device__ float  g_P  [BB*NCH*DD];
__device__ float  g_H  [BB*NCH*DD];
__device__ float  g_I  [BB*NCH*DD];
__device__ float  g_bg [4*DD];      // gate bias, layout [f | i,g interleaved | o]
__device__ float  g_bff[2*DFF_];    // ffn bias, interleaved [bfc_j, bfa_j]

__device__ __half g_xn [MM*DD];
__device__ __half g_xn2[MM*DD];
__device__ __half g_hff[MM*DFF_];
__device__ __half g_wgt[4*DD*DD];   // [4096,1024] K-major, rows [f | i,g ilv | o]
__device__ __half g_wff[2*DFF_*DD]; // [8192,1024] K-major, rows interleaved (fc,fca)
__device__ __half g_wout[DD*DFF_];  // [1024,4096] K-major

// ---------------- asm helpers ----------------
__device__ __forceinline__ uint32_t smem_to_u32(const void* p) {
    uint32_t a;
    asm("{ .reg .u64 t; cvta.to.shared.u64 t, %1; cvt.u32.u64 %0, t; }" : "=r"(a) : "l"(p));
    return a;
}
__device__ __forceinline__ void cp_async16(uint32_t sa, const void* gp) {
    asm volatile("cp.async.cg.shared.global [%0], [%1], 16;" :: "r"(sa), "l"(gp));
}
__device__ __forceinline__ void cp_commit() {
    asm volatile("cp.async.commit_group;" ::: "memory");
}
__device__ __forceinline__ void ldsm4(uint32_t* d, uint32_t addr) {
    asm volatile("ldmatrix.sync.aligned.m8n8.x4.shared.b16 {%0,%1,%2,%3}, [%4];"
        : "=r"(d[0]), "=r"(d[1]), "=r"(d[2]), "=r"(d[3]) : "r"(addr));
}
__device__ __forceinline__ void mma_f16(float* c, const uint32_t* a, const uint32_t* b) {
    asm volatile("mma.sync.aligned.m16n8k16.row.col.f32.f16.f16.f32 "
        "{%0,%1,%2,%3}, {%4,%5,%6,%7}, {%8,%9}, {%0,%1,%2,%3};"
        : "+f"(c[0]), "+f"(c[1]), "+f"(c[2]), "+f"(c[3])
        : "r"(a[0]), "r"(a[1]), "r"(a[2]), "r"(a[3]), "r"(b[0]), "r"(b[1]));
}
__device__ __forceinline__ float sigmoidf_(float v) { return 1.f / (1.f + expf(-v)); }

// SW128-style swizzle for [rows][64 fp16] tiles (128B rows, 8 x 16B chunks)
__device__ __forceinline__ uint32_t swz(int row, int c) {
    return (uint32_t)(row * 128 + (((c) ^ (row & 7)) << 4));
}

// ---------------- fused packing + RMSNorm1 kernel ----------------
// bids [0,16384):      weight transpose tiles (pack)
// bids [16384,16416):  bias packing
// bids [16416,32800):  rmsnorm1 rows (row = bid - 16416)
#define PACK_BLKS 16416
__global__ void pack_norm(const float* __restrict__ wf,  const float* __restrict__ wi,
                          const float* __restrict__ wg,  const float* __restrict__ wo,
                          const float* __restrict__ wfc, const float* __restrict__ wfa,
                          const float* __restrict__ wou,
                          const float* __restrict__ bf,  const float* __restrict__ bi,
                          const float* __restrict__ bg,  const float* __restrict__ bo,
                          const float* __restrict__ bfc, const float* __restrict__ bfa,
                          const float* __restrict__ x,   const float* __restrict__ n1w,
                          __half* __restrict__ WGT, __half* __restrict__ WFF,
                          __half* __restrict__ WOUT,
                          float* __restrict__ BG, float* __restrict__ BFF,
                          __half* __restrict__ XN)
{
    int bid = blockIdx.x;
    int tid = threadIdx.x;        // 256 flat

    __shared__ float t[32][33];   // pack path
    __shared__ float red[8];      // norm path
    __shared__ float s_scale;

    if (bid >= PACK_BLKS) {
        // ---- RMSNorm1 row ----
        int row = bid - PACK_BLKS;
        const float4* xv = reinterpret_cast<const float4*>(x + (size_t)row * DD);
        const float4* wv = reinterpret_cast<const float4*>(n1w);
        float4 v = xv[tid];
        float ss = v.x*v.x + v.y*v.y + v.z*v.z + v.w*v.w;
        #pragma unroll
        for (int of = 16; of > 0; of >>= 1) ss += __shfl_xor_sync(0xffffffffu, ss, of);
        if ((tid & 31) == 0) red[tid >> 5] = ss;
        __syncthreads();
        if (tid == 0) {
            float s = 0.f;
            #pragma unroll
            for (int i = 0; i < 8; i++) s += red[i];
            s_scale = rsqrtf(s / (float)DD + 1e-6f);
        }
        __syncthreads();
        float s = s_scale;
        float4 w4 = wv[tid];
        __half2* ov = reinterpret_cast<__half2*>(XN + (size_t)row * DD);
        ov[tid*2]   = __floats2half2_rn(v.x*s*w4.x, v.y*s*w4.y);
        ov[tid*2+1] = __floats2half2_rn(v.z*s*w4.z, v.w*s*w4.w);
        return;
    }

    if (bid >= 16384) {
        // ---- bias pack: 32 blocks x 256 threads = 8192 ----
        int n = (bid - 16384) * 256 + tid;
        if (n < 4 * DD) {
            float v;
            if (n < DD)            v = bf[n];
            else if (n < 3 * DD) { int q = n - DD; v = (q & 1) ? bg[q >> 1] : bi[q >> 1]; }
            else                   v = bo[n - 3 * DD];
            BG[n] = v;
        }
        BFF[n] = (n & 1) ? bfa[n >> 1] : bfc[n >> 1];
        return;
    }

    // ---- weight transpose tile ----
    int tx = tid & 31, ty = tid >> 5;   // (32, 8)
    const float *S0, *S1; __half* T; int Kd, Ns, bx, by; bool pair;
    if (bid < 1024)       { S0 = wf;  S1 = nullptr; T = WGT;             Kd = DD;   Ns = DD;   pair = false; int l = bid;          bx = l % 32;  by = l / 32; }
    else if (bid < 3072)  { S0 = wi;  S1 = wg;      T = WGT + 1024 * DD; Kd = DD;   Ns = DD;   pair = true;  int l = bid - 1024;   bx = l % 64;  by = l / 64; }
    else if (bid < 4096)  { S0 = wo;  S1 = nullptr; T = WGT + 3072 * DD; Kd = DD;   Ns = DD;   pair = false; int l = bid - 3072;   bx = l % 32;  by = l / 32; }
    else if (bid < 12288) { S0 = wfc; S1 = wfa;     T = WFF;             Kd = DD;   Ns = DFF_; pair = true;  int l = bid - 4096;   bx = l % 256; by = l / 256; }
    else                  { S0 = wou; S1 = nullptr; T = WOUT;            Kd = DFF_; Ns = DD;   pair = false; int l = bid - 12288;  bx = l % 32;  by = l / 32; }

    int n0 = bx * 32, k0 = by * 32;
    const float* S = S0; int col = n0 + tx;
    if (pair) { S = ((n0 + tx) & 1) ? S1 : S0; col = (n0 + tx) >> 1; }
    #pragma unroll
    for (int i = 0; i < 32; i += 8)
        t[ty + i][tx] = S[(size_t)(k0 + ty + i) * Ns + col];
    __syncthreads();
    #pragma unroll
    for (int i = 0; i < 32; i += 8)
        T[(size_t)(n0 + ty + i) * Kd + k0 + tx] = __float2half_rn(t[tx][ty + i]);
}

// ---------------- pipelined HMMA GEMM: 256 threads, 2 CTAs/SM ----------------
// C[M,N] = ACT(A @ B'^T + bias)  A fp16 [M,K] row-major, B' fp16 [N,K] row-major
// ACT 5: gates, N=4096 layout [f | i,g ilv | o]: a->C fp32, bv->C1h fp16, o->C2h fp16
// ACT 6: fused FFN-up, N=8192 ilv (fc,fca): hff=fc*silu(fca) -> Ch fp16
constexpr int BM = 128, BN = 128, BK = 64, STAGES = 3, NT = 256;
constexpr int ASTG = BM * BK * 2;     // 16 KB
constexpr int BSTG = BN * BK * 2;     // 16 KB
constexpr int STG  = ASTG + BSTG;     // 32 KB
constexpr int GSMEM = STAGES * STG;   // 96 KB -> 2 CTAs/SM

template<int ACT>
__global__ __launch_bounds__(NT, 2) void tc_gemm(
    const __half* __restrict__ A, const __half* __restrict__ Bw,
    const float* __restrict__ bias, const float* __restrict__ aux,
    float* __restrict__ C, __half* __restrict__ Ch,
    __half* __restrict__ C1h, __half* __restrict__ C2h,
    int M, int N, int K)
{
    extern __shared__ __align__(128) char smem[];
    uint32_t su = smem_to_u32(smem);
    int tid = threadIdx.x, wid = tid >> 5, lane = tid & 31;

    // supertile raster (8 m-tiles per group) for L2 reuse
    int tn = N / BN;
    int per = 8 * tn, grp = blockIdx.x / per, rr = blockIdx.x % per;
    int m0 = (grp * 8 + (rr % 8)) * BM;
    int n0 = (rr / 8) * BN;

    const __half* Ab = A  + (size_t)m0 * K;
    const __half* Bb = Bw + (size_t)n0 * K;

    uint32_t sAo[4], gAo[4];
    #pragma unroll
    for (int j = 0; j < 4; j++) {
        int idx = tid + j * NT, r = idx >> 3, c = idx & 7;
        sAo[j] = swz(r, c); gAo[j] = (uint32_t)(r * K + c * 8);
    }

    int wm = (wid & 1) * 64, wn = (wid >> 1) * 32;
    int rA128[4], rA7[4], rB128[2], rB7[2];
    int cA = lane >> 4;
    int cB = (lane >> 3) & 1;
    #pragma unroll
    for (int i = 0; i < 4; i++) {
        int ra = wm + i * 16 + (lane & 15);
        rA128[i] = ra * 128; rA7[i] = ra & 7;
    }
    #pragma unroll
    for (int p = 0; p < 2; p++) {
        int rb = wn + p * 16 + (lane & 7) + ((lane >> 4) << 3);
        rB128[p] = rb * 128; rB7[p] = rb & 7;
    }

    float acc[4][4][4];
    #pragma unroll
    for (int i = 0; i < 4; i++)
        #pragma unroll
        for (int j = 0; j < 4; j++)
            #pragma unroll
            for (int q = 0; q < 4; q++) acc[i][j][q] = 0.f;

    const int NK = K / BK;

    #pragma unroll
    for (int s = 0; s < STAGES - 1; s++) {
        uint32_t sA = su + s * STG, sB = sA + ASTG;
        int k0 = s * BK;
        #pragma unroll
        for (int j = 0; j < 4; j++) {
            cp_async16(sA + sAo[j], Ab + gAo[j] + k0);
            cp_async16(sB + sAo[j], Bb + gAo[j] + k0);
        }
        cp_commit();
    }

    int cs = 0, ls = STAGES - 1;
    for (int kt = 0; kt < NK; kt++) {
        asm volatile("cp.async.wait_group %0;" :: "n"(STAGES - 2) : "memory");
        __syncthreads();

        int lt = kt + STAGES - 1;
        if (lt < NK) {
            uint32_t sA = su + ls * STG, sB = sA + ASTG;
            int k0 = lt * BK;
            #pragma unroll
            for (int j = 0; j < 4; j++) {
                cp_async16(sA + sAo[j], Ab + gAo[j] + k0);
                cp_async16(sB + sAo[j], Bb + gAo[j] + k0);
            }
        }
        cp_commit();
        if (++ls == STAGES) ls = 0;

        uint32_t sA = su + cs * STG, sB = sA + ASTG;
        if (++cs == STAGES) cs = 0;
        #pragma unroll
        for (int kk = 0; kk < 4; kk++) {
            uint32_t a[4][4], b[2][4];
            #pragma unroll
            for (int i = 0; i < 4; i++)
                ldsm4(a[i], sA + rA128[i] + (((kk * 2 + cA) ^ rA7[i]) << 4));
            #pragma unroll
            for (int p = 0; p < 2; p++)
                ldsm4(b[p], sB + rB128[p] + (((kk * 2 + cB) ^ rB7[p]) << 4));
            #pragma unroll
            for (int p = 0; p < 2; p++)
                #pragma unroll
                for (int i = 0; i < 4; i++) {
                    mma_f16(acc[i][2*p],     a[i], b[p]);
                    mma_f16(acc[i][2*p + 1], a[i], b[p] + 2);
                }
        }
    }

    // ---- fused epilogue ----
    #pragma unroll
    for (int i = 0; i < 4; i++) {
        int r0 = m0 + wm + i * 16 + (lane >> 2);
        #pragma unroll
        for (int j = 0; j < 4; j++) {
            int c0 = n0 + wn + j * 8 + (lane & 3) * 2;
            float b0 = bias[c0], b1 = bias[c0 + 1];
            #pragma unroll
            for (int h = 0; h < 2; h++) {
                int r = r0 + h * 8;
                float v0 = acc[i][j][2*h]     + b0;
                float v1 = acc[i][j][2*h + 1] + b1;
                if (ACT == 5) {
                    if (c0 < 1024) {
                        *reinterpret_cast<float2*>(&C[(size_t)r * DD + c0]) =
                            make_float2(sigmoidf_(v0), sigmoidf_(v1));
                    } else if (c0 < 3072) {
                        C1h[(size_t)r * DD + ((c0 - 1024) >> 1)] =
                            __float2half_rn(tanhf(v0) * sigmoidf_(v1));
                    } else {
                        *reinterpret_cast<__half2*>(&C2h[(size_t)r * DD + (c0 - 3072)]) =
                            __floats2half2_rn(sigmoidf_(v0), sigmoidf_(v1));
                    }
                } else if (ACT == 6) {
                    Ch[(size_t)r * DFF_ + (c0 >> 1)] =
                        __float2half_rn(v0 * (v1 * sigmoidf_(v1)));
                }
            }
        }
    }
}

// ---------------- BN=64 GEMM variant for the down-projection ----------------
// C = A @ B'^T + bias + aux  (fp32 out). Warp tile 64x16; grid 2048 CTAs
// (M/128 x N/64) -> 6.92 waves instead of 3.46 -> tail waste ~1%.
constexpr int BN2 = 64;
constexpr int BSTG2 = BN2 * BK * 2;        // 8 KB
constexpr int STG2  = ASTG + BSTG2;        // 24 KB
constexpr int GSMEM2 = STAGES * STG2;      // 72 KB -> 2 CTAs/SM

__global__ __launch_bounds__(NT, 2) void tc_gemm_n64(
    const __half* __restrict__ A, const __half* __restrict__ Bw,
    const float* __restrict__ bias, const float* __restrict__ aux,
    float* __restrict__ C, int M, int N, int K)
{
    extern __shared__ __align__(128) char smem[];
    uint32_t su = smem_to_u32(smem);
    int tid = threadIdx.x, wid = tid >> 5, lane = tid & 31;

    int tn = N / BN2;
    int per = 8 * tn, grp = blockIdx.x / per, rr = blockIdx.x % per;
    int m0 = (grp * 8 + (rr % 8)) * BM;
    int n0 = (rr / 8) * BN2;

    const __half* Ab = A  + (size_t)m0 * K;
    const __half* Bb = Bw + (size_t)n0 * K;

    // cp.async: A 4 chunks/thread, B 2 chunks/thread
    uint32_t sAo[4], gAo[4], sBo[2], gBo[2];
    #pragma unroll
    for (int j = 0; j < 4; j++) {
        int idx = tid + j * NT, r = idx >> 3, c = idx & 7;
        sAo[j] = swz(r, c); gAo[j] = (uint32_t)(r * K + c * 8);
    }
    #pragma unroll
    for (int j = 0; j < 2; j++) {
        int idx = tid + j * NT, r = idx >> 3, c = idx & 7;
        sBo[j] = swz(r, c); gBo[j] = (uint32_t)(r * K + c * 8);
    }

    // warp layout: 2 (m) x 4 (n); warp tile 64x16
    int wm = (wid & 1) * 64, wn = (wid >> 1) * 16;
    int rA128[4], rA7[4];
    int cA = lane >> 4;
    int cB = (lane >> 3) & 1;
    #pragma unroll
    for (int i = 0; i < 4; i++) {
        int ra = wm + i * 16 + (lane & 15);
        rA128[i] = ra * 128; rA7[i] = ra & 7;
    }
    int rb = wn + (lane & 7) + ((lane >> 4) << 3);
    int rB128 = rb * 128, rB7 = rb & 7;

    float acc[4][2][4];
    #pragma unroll
    for (int i = 0; i < 4; i++)
        #pragma unroll
        for (int j = 0; j < 2; j++)
            #pragma unroll
            for (int q = 0; q < 4; q++) acc[i][j][q] = 0.f;

    const int NK = K / BK;

    #pragma unroll
    for (int s = 0; s < STAGES - 1; s++) {
        uint32_t sA = su + s * STG2, sB = sA + ASTG;
        int k0 = s * BK;
        #pragma unroll
        for (int j = 0; j < 4; j++) cp_async16(sA + sAo[j], Ab + gAo[j] + k0);
        #pragma unroll
        for (int j = 0; j < 2; j++) cp_async16(sB + sBo[j], Bb + gBo[j] + k0);
        cp_commit();
    }

    int cs = 0, ls = STAGES - 1;
    for (int kt = 0; kt < NK; kt++) {
        asm volatile("cp.async.wait_group %0;" :: "n"(STAGES - 2) : "memory");
        __syncthreads();

        int lt = kt + STAGES - 1;
        if (lt < NK) {
            uint32_t sA = su + ls * STG2, sB = sA + ASTG;
            int k0 = lt * BK;
            #pragma unroll
            for (int j = 0; j < 4; j++) cp_async16(sA + sAo[j], Ab + gAo[j] + k0);
            #pragma unroll
            for (int j = 0; j < 2; j++) cp_async16(sB + sBo[j], Bb + gBo[j] + k0);
        }
        cp_commit();
        if (++ls == STAGES) ls = 0;

        uint32_t sA = su + cs * STG2, sB = sA + ASTG;
        if (++cs == STAGES) cs = 0;
        #pragma unroll
        for (int kk = 0; kk < 4; kk++) {
            uint32_t a[4][4], b[4];
            #pragma unroll
            for (int i = 0; i < 4; i++)
                ldsm4(a[i], sA + rA128[i] + (((kk * 2 + cA) ^ rA7[i]) << 4));
            ldsm4(b, sB + rB128 + (((kk * 2 + cB) ^ rB7) << 4));
            #pragma unroll
            for (int i = 0; i < 4; i++) {
                mma_f16(acc[i][0], a[i], b);
                mma_f16(acc[i][1], a[i], b + 2);
            }
        }
    }

    // ---- epilogue: + bias + aux (x1 residual) ----
    #pragma unroll
    for (int i = 0; i < 4; i++) {
        int r0 = m0 + wm + i * 16 + (lane >> 2);
        #pragma unroll
        for (int j = 0; j < 2; j++) {
            int c0 = n0 + wn + j * 8 + (lane & 3) * 2;
            float b0 = bias[c0], b1 = bias[c0 + 1];
            #pragma unroll
            for (int h = 0; h < 2; h++) {
                int r = r0 + h * 8;
                size_t idx = (size_t)r * N + c0;
                float2 au = *reinterpret_cast<const float2*>(&aux[idx]);
                *reinterpret_cast<float2*>(&C[idx]) =
                    make_float2(acc[i][j][2*h] + b0 + au.x,
                                acc[i][j][2*h + 1] + b1 + au.y);
            }
        }
    }
}

// ---------------- chunked linear-recurrence scan ----------------
__global__ void scan_pass1(const float* __restrict__ aG, const __half* __restrict__ bVh,
                           float* __restrict__ Pb, float* __restrict__ Hb)
{
    int g = blockIdx.x * blockDim.x + threadIdx.x;    // BB*NCH*DD/2 threads
    int d2 = g & (DD/2 - 1);
    int c  = (g >> 9) & (NCH - 1);
    int b  = g >> 16;
    size_t base = ((size_t)b * LL + (size_t)c * CHUNK) * DD + d2 * 2;
    float2 P = make_float2(1.f, 1.f), hh = make_float2(0.f, 0.f);
    #pragma unroll 4
    for (int t = 0; t < CHUNK; t++) {
        size_t idx = base + (size_t)t * DD;
        float2 a  = *reinterpret_cast<const float2*>(aG + idx);
        float2 bv = __half22float2(*reinterpret_cast<const __half2*>(bVh + idx));
        P.x *= a.x; P.y *= a.y;
        hh.x = fmaf(a.x, hh.x, bv.x);
        hh.y = fmaf(a.y, hh.y, bv.y);
    }
    *reinterpret_cast<float2*>(Pb + (size_t)g * 2) = P;
    *reinterpret_cast<float2*>(Hb + (size_t)g * 2) = hh;
}

// pass2: parallel Kogge-Stone scan over the 128 chunks.
__global__ __launch_bounds__(128) void scan_pass2(
    const float* __restrict__ Pb, const float* __restrict__ Hb,
    const float* __restrict__ h0, float* __restrict__ Ib)
{
    int bd = blockIdx.x;            // 0..BB*DD-1
    int b = bd >> 10, d = bd & (DD - 1);
    int c = threadIdx.x;            // chunk 0..127
    int lane = c & 31, w = c >> 5;

    size_t j = ((size_t)(b * NCH + c)) * DD + d;
    float P = Pb[j], H = Hb[j];

    #pragma unroll
    for (int s = 1; s < 32; s <<= 1) {
        float Po = __shfl_up_sync(0xffffffffu, P, s);
        float Ho = __shfl_up_sync(0xffffffffu, H, s);
        if (lane >= s) { H = fmaf(Ho, P, H); P = Po * P; }
    }

    __shared__ float wp[4], wh[4];
    if (lane == 31) { wp[w] = P; wh[w] = H; }
    __syncthreads();
    float Pp = 1.f, Hp = 0.f;
    #pragma unroll
    for (int i = 0; i < 3; i++)
        if (i < w) { Hp = fmaf(Hp, wp[i], wh[i]); Pp *= wp[i]; }

    float Pe = __shfl_up_sync(0xffffffffu, P, 1);
    float He = __shfl_up_sync(0xffffffffu, H, 1);
    if (lane == 0) { Pe = 1.f; He = 0.f; }

    float Pt = Pp * Pe;
    float Ht = fmaf(Hp, Pe, He);
    Ib[j] = fmaf(Pt, h0[d], Ht);
}

// pass3 fused with RMSNorm2: one block (512 threads) owns a full D=1024 row
// for one (b, chunk). Writes x1 (fp32) AND xn2 (fp16, normalized) directly.
__global__ __launch_bounds__(512) void scan_pass3n(
    const float* __restrict__ aG, const __half* __restrict__ bVh,
    const __half* __restrict__ oSh, const float* __restrict__ x,
    const float* __restrict__ Ib, const float* __restrict__ w2,
    float* __restrict__ x1, __half* __restrict__ xn2)
{
    int b = blockIdx.x >> 7;            // 4 batches
    int c = blockIdx.x & 127;           // 128 chunks
    int tid = threadIdx.x;              // 512 threads, 2 d's each
    int d0 = tid * 2;

    __shared__ float red[16];
    __shared__ float s_scale;

    size_t base = ((size_t)b * LL + (size_t)c * CHUNK) * DD + d0;
    float2 hh = *reinterpret_cast<const float2*>(Ib + ((size_t)(b * NCH + c) * DD + d0));
    float2 w  = *reinterpret_cast<const float2*>(w2 + d0);

    for (int t = 0; t < CHUNK; t++) {
        size_t idx = base + (size_t)t * DD;
        float2 a  = *reinterpret_cast<const float2*>(aG + idx);
        float2 bv = __half22float2(*reinterpret_cast<const __half2*>(bVh + idx));
        float2 os = __half22float2(*reinterpret_cast<const __half2*>(oSh + idx));
        float2 xv = *reinterpret_cast<const float2*>(x + idx);
        hh.x = fmaf(a.x, hh.x, bv.x);
        hh.y = fmaf(a.y, hh.y, bv.y);
        float y0 = tanhf(hh.x) * os.x + xv.x;
        float y1 = tanhf(hh.y) * os.y + xv.y;
        *reinterpret_cast<float2*>(x1 + idx) = make_float2(y0, y1);

        float ss = y0 * y0 + y1 * y1;
        #pragma unroll
        for (int of = 16; of > 0; of >>= 1) ss += __shfl_xor_sync(0xffffffffu, ss, of);
        if ((tid & 31) == 0) red[tid >> 5] = ss;
        __syncthreads();
        if (tid < 32) {
            float v = (tid < 16) ? red[tid] : 0.f;
            #pragma unroll
            for (int of = 8; of > 0; of >>= 1) v += __shfl_xor_sync(0xffffffffu, v, of);
            if (tid == 0) s_scale = rsqrtf(v / (float)DD + 1e-6f);
        }
        __syncthreads();
        float s = s_scale;
        *reinterpret_cast<__half2*>(xn2 + idx) =
            __floats2half2_rn(y0 * s * w.x, y1 * s * w.y);
        __syncthreads();   // protect s_scale for next t
    }
}

// ---------------- launcher ----------------
extern "C" void kernel_launch(void* const* d_in, const int* in_sizes, int n_in,
                              void* d_out, int out_size)
{
    (void)in_sizes; (void)n_in; (void)out_size;
    const float* x   = (const float*)d_in[0];
    const float* wf  = (const float*)d_in[1];
    const float* bf_ = (const float*)d_in[2];
    const float* wi  = (const float*)d_in[3];
    const float* bi_ = (const float*)d_in[4];
    const float* wg  = (const float*)d_in[5];
    const float* bg_ = (const float*)d_in[6];
    const float* wo  = (const float*)d_in[7];
    const float* bo_ = (const float*)d_in[8];
    const float* h0  = (const float*)d_in[9];
    const float* n1w = (const float*)d_in[10];
    const float* n2w = (const float*)d_in[11];
    const float* wfc = (const float*)d_in[12];
    const float* bfc = (const float*)d_in[13];
    const float* wfa = (const float*)d_in[14];
    const float* bfa = (const float*)d_in[15];
    const float* wou = (const float*)d_in[16];
    const float* bou = (const float*)d_in[17];
    float* out = (float*)d_out;

    float *ga, *x1, *P, *H, *I, *bg4, *bff;
    cudaGetSymbolAddress((void**)&ga,  g_a);
    cudaGetSymbolAddress((void**)&x1,  g_x1);
    cudaGetSymbolAddress((void**)&P,   g_P);
    cudaGetSymbolAddress((void**)&H,   g_H);
    cudaGetSymbolAddress((void**)&I,   g_I);
    cudaGetSymbolAddress((void**)&bg4, g_bg);
    cudaGetSymbolAddress((void**)&bff, g_bff);

    __half *gbvh, *goh, *xn, *xn2, *hff, *wgt, *wff, *wout_;
    cudaGetSymbolAddress((void**)&gbvh, g_bvh);
    cudaGetSymbolAddress((void**)&goh,  g_oh);
    cudaGetSymbolAddress((void**)&xn,   g_xn);
    cudaGetSymbolAddress((void**)&xn2,  g_xn2);
    cudaGetSymbolAddress((void**)&hff,  g_hff);
    cudaGetSymbolAddress((void**)&wgt,  g_wgt);
    cudaGetSymbolAddress((void**)&wff,  g_wff);
    cudaGetSymbolAddress((void**)&wout_,g_wout);

    cudaFuncSetAttribute(tc_gemm<5>, cudaFuncAttributeMaxDynamicSharedMemorySize, GSMEM);
    cudaFuncSetAttribute(tc_gemm<6>, cudaFuncAttributeMaxDynamicSharedMemorySize, GSMEM);
    cudaFuncSetAttribute(tc_gemm_n64, cudaFuncAttributeMaxDynamicSharedMemorySize, GSMEM2);

    // 0) fused weight/bias packing + RMSNorm1 (single launch)
    pack_norm<<<PACK_BLKS + MM, 256>>>(wf, wi, wg, wo, wfc, wfa, wou,
                                       bf_, bi_, bg_, bo_, bfc, bfa,
                                       x, n1w,
                                       wgt, wff, wout_, bg4, bff, xn);

    // 1) gate GEMM (N=4096) -> a (fp32), bv (fp16), o (fp16)
    int gGates = (MM/BM) * ((4*DD)/BN);
    tc_gemm<5><<<gGates, NT, GSMEM>>>(xn, wgt, bg4, nullptr, ga, nullptr, gbvh, goh,
                                      MM, 4*DD, DD);

    // 2) scan + output gate + residual + fused RMSNorm2 -> x1 (fp32), xn2 (fp16)
    scan_pass1<<<(BB*NCH*DD/2)/256, 256>>>(ga, gbvh, P, H);
    scan_pass2<<<BB*DD, 128>>>(P, H, h0, I);
    scan_pass3n<<<BB*NCH, 512>>>(ga, gbvh, goh, x, I, n2w, x1, xn2);

    // 3) fused FFN-up (N=8192, interleaved) -> hff fp16
    int gFF = (MM/BM) * ((2*DFF_)/BN);
    tc_gemm<6><<<gFF, NT, GSMEM>>>(xn2, wff, bff, nullptr, nullptr, hff, nullptr, nullptr,
                                   MM, 2*DFF_, DD);

    // 4) down-proj (BN=64 variant: 2048 CTAs, minimal wave tail) + b_out + x1 -> d_out
    int gOut = (MM/BM) * (DD/BN2);
    tc_gemm_n64<<<gOut, NT, GSMEM2>>>(hff, wout_, bou, x1, out, MM, DD, DFF_);
}

// round 15
// speedup vs baseline: 1.0936x; 1.0936x over previous
#include <cuda_runtime.h>
#include <cuda_fp16.h>
#include <cstdint>

// Problem shape (fixed)
#define BB   4
#define LL   4096
#define DD   1024
#define DFF_ 4096
#define MM   (BB*LL)        // 16384 token rows
#define NCH  128
#define CHUNK 32

// ---------------- scratch (device globals: allocation-free) ----------------
__device__ float  g_a  [MM*DD];     // sigmoid(forget)  (fp32: 1/(1-a) error amplification)
__device__ __half g_bvh[MM*DD];     // tanh(input)*sigmoid(igate)
__device__ __half g_oh [MM*DD];     // sigmoid(ogate)
__device__ float  g_x1 [MM*DD];
__device__ float  g_P  [BB*NCH*DD];
__device__ float  g_H  [BB*NCH*DD];
__device__ float  g_I  [BB*NCH*DD];
__device__ float  g_bg [4*DD];      // gate bias, layout [f | i,g interleaved | o]
__device__ float  g_bff[2*DFF_];    // ffn bias, interleaved [bfc_j, bfa_j]

__device__ __half g_xn [MM*DD];
__device__ __half g_xn2[MM*DD];
__device__ __half g_hff[MM*DFF_];
__device__ __half g_wgt[4*DD*DD];   // [4096,1024] K-major, rows [f | i,g ilv | o]
__device__ __half g_wff[2*DFF_*DD]; // [8192,1024] K-major, rows interleaved (fc,fca)
__device__ __half g_wout[DD*DFF_];  // [1024,4096] K-major

// ---------------- asm helpers ----------------
__device__ __forceinline__ uint32_t smem_to_u32(const void* p) {
    uint32_t a;
    asm("{ .reg .u64 t; cvta.to.shared.u64 t, %1; cvt.u32.u64 %0, t; }" : "=r"(a) : "l"(p));
    return a;
}
__device__ __forceinline__ void cp_async16(uint32_t sa, const void* gp) {
    asm volatile("cp.async.cg.shared.global [%0], [%1], 16;" :: "r"(sa), "l"(gp));
}
__device__ __forceinline__ void cp_commit() {
    asm volatile("cp.async.commit_group;" ::: "memory");
}
__device__ __forceinline__ void ldsm4(uint32_t* d, uint32_t addr) {
    asm volatile("ldmatrix.sync.aligned.m8n8.x4.shared.b16 {%0,%1,%2,%3}, [%4];"
        : "=r"(d[0]), "=r"(d[1]), "=r"(d[2]), "=r"(d[3]) : "r"(addr));
}
__device__ __forceinline__ void mma_f16(float* c, const uint32_t* a, const uint32_t* b) {
    asm volatile("mma.sync.aligned.m16n8k16.row.col.f32.f16.f16.f32 "
        "{%0,%1,%2,%3}, {%4,%5,%6,%7}, {%8,%9}, {%0,%1,%2,%3};"
        : "+f"(c[0]), "+f"(c[1]), "+f"(c[2]), "+f"(c[3])
        : "r"(a[0]), "r"(a[1]), "r"(a[2]), "r"(a[3]), "r"(b[0]), "r"(b[1]));
}
__device__ __forceinline__ float sigmoidf_(float v) { return 1.f / (1.f + expf(-v)); }

// SW128-style swizzle for [rows][64 fp16] tiles (128B rows, 8 x 16B chunks)
__device__ __forceinline__ uint32_t swz(int row, int c) {
    return (uint32_t)(row * 128 + (((c) ^ (row & 7)) << 4));
}

// ---------------- fused packing + RMSNorm1 kernel ----------------
// bids [0,16384):      weight transpose tiles (pack)
// bids [16384,16416):  bias packing
// bids [16416,32800):  rmsnorm1 rows (row = bid - 16416)
#define PACK_BLKS 16416
__global__ void pack_norm(const float* __restrict__ wf,  const float* __restrict__ wi,
                          const float* __restrict__ wg,  const float* __restrict__ wo,
                          const float* __restrict__ wfc, const float* __restrict__ wfa,
                          const float* __restrict__ wou,
                          const float* __restrict__ bf,  const float* __restrict__ bi,
                          const float* __restrict__ bg,  const float* __restrict__ bo,
                          const float* __restrict__ bfc, const float* __restrict__ bfa,
                          const float* __restrict__ x,   const float* __restrict__ n1w,
                          __half* __restrict__ WGT, __half* __restrict__ WFF,
                          __half* __restrict__ WOUT,
                          float* __restrict__ BG, float* __restrict__ BFF,
                          __half* __restrict__ XN)
{
    int bid = blockIdx.x;
    int tid = threadIdx.x;        // 256 flat

    __shared__ float t[32][33];   // pack path
    __shared__ float red[8];      // norm path
    __shared__ float s_scale;

    if (bid >= PACK_BLKS) {
        // ---- RMSNorm1 row ----
        int row = bid - PACK_BLKS;
        const float4* xv = reinterpret_cast<const float4*>(x + (size_t)row * DD);
        const float4* wv = reinterpret_cast<const float4*>(n1w);
        float4 v = xv[tid];
        float ss = v.x*v.x + v.y*v.y + v.z*v.z + v.w*v.w;
        #pragma unroll
        for (int of = 16; of > 0; of >>= 1) ss += __shfl_xor_sync(0xffffffffu, ss, of);
        if ((tid & 31) == 0) red[tid >> 5] = ss;
        __syncthreads();
        if (tid == 0) {
            float s = 0.f;
            #pragma unroll
            for (int i = 0; i < 8; i++) s += red[i];
            s_scale = rsqrtf(s / (float)DD + 1e-6f);
        }
        __syncthreads();
        float s = s_scale;
        float4 w4 = wv[tid];
        __half2* ov = reinterpret_cast<__half2*>(XN + (size_t)row * DD);
        ov[tid*2]   = __floats2half2_rn(v.x*s*w4.x, v.y*s*w4.y);
        ov[tid*2+1] = __floats2half2_rn(v.z*s*w4.z, v.w*s*w4.w);
        return;
    }

    if (bid >= 16384) {
        // ---- bias pack: 32 blocks x 256 threads = 8192 ----
        int n = (bid - 16384) * 256 + tid;
        if (n < 4 * DD) {
            float v;
            if (n < DD)            v = bf[n];
            else if (n < 3 * DD) { int q = n - DD; v = (q & 1) ? bg[q >> 1] : bi[q >> 1]; }
            else                   v = bo[n - 3 * DD];
            BG[n] = v;
        }
        BFF[n] = (n & 1) ? bfa[n >> 1] : bfc[n >> 1];
        return;
    }

    // ---- weight transpose tile ----
    int tx = tid & 31, ty = tid >> 5;   // (32, 8)
    const float *S0, *S1; __half* T; int Kd, Ns, bx, by; bool pair;
    if (bid < 1024)       { S0 = wf;  S1 = nullptr; T = WGT;             Kd = DD;   Ns = DD;   pair = false; int l = bid;          bx = l % 32;  by = l / 32; }
    else if (bid < 3072)  { S0 = wi;  S1 = wg;      T = WGT + 1024 * DD; Kd = DD;   Ns = DD;   pair = true;  int l = bid - 1024;   bx = l % 64;  by = l / 64; }
    else if (bid < 4096)  { S0 = wo;  S1 = nullptr; T = WGT + 3072 * DD; Kd = DD;   Ns = DD;   pair = false; int l = bid - 3072;   bx = l % 32;  by = l / 32; }
    else if (bid < 12288) { S0 = wfc; S1 = wfa;     T = WFF;             Kd = DD;   Ns = DFF_; pair = true;  int l = bid - 4096;   bx = l % 256; by = l / 256; }
    else                  { S0 = wou; S1 = nullptr; T = WOUT;            Kd = DFF_; Ns = DD;   pair = false; int l = bid - 12288;  bx = l % 32;  by = l / 32; }

    int n0 = bx * 32, k0 = by * 32;
    const float* S = S0; int col = n0 + tx;
    if (pair) { S = ((n0 + tx) & 1) ? S1 : S0; col = (n0 + tx) >> 1; }
    #pragma unroll
    for (int i = 0; i < 32; i += 8)
        t[ty + i][tx] = S[(size_t)(k0 + ty + i) * Ns + col];
    __syncthreads();
    #pragma unroll
    for (int i = 0; i < 32; i += 8)
        T[(size_t)(n0 + ty + i) * Kd + k0 + tx] = __float2half_rn(t[tx][ty + i]);
}

// ---------------- pipelined HMMA GEMM: 256 threads, 2 CTAs/SM ----------------
// C[M,N] = ACT(A @ B'^T + bias)  A fp16 [M,K] row-major, B' fp16 [N,K] row-major
// ACT 4: v+aux -> C (down-proj, fp32 out)
// ACT 5: gates, N=4096 layout [f | i,g ilv | o]: a->C fp32, bv->C1h fp16, o->C2h fp16
// ACT 6: fused FFN-up, N=8192 ilv (fc,fca): hff=fc*silu(fca) -> Ch fp16
constexpr int BM = 128, BN = 128, BK = 64, STAGES = 3, NT = 256;
constexpr int ASTG = BM * BK * 2;     // 16 KB
constexpr int BSTG = BN * BK * 2;     // 16 KB
constexpr int STG  = ASTG + BSTG;     // 32 KB
constexpr int GSMEM = STAGES * STG;   // 96 KB -> 2 CTAs/SM

template<int ACT>
__global__ __launch_bounds__(NT, 2) void tc_gemm(
    const __half* __restrict__ A, const __half* __restrict__ Bw,
    const float* __restrict__ bias, const float* __restrict__ aux,
    float* __restrict__ C, __half* __restrict__ Ch,
    __half* __restrict__ C1h, __half* __restrict__ C2h,
    int M, int N, int K)
{
    extern __shared__ __align__(128) char smem[];
    uint32_t su = smem_to_u32(smem);
    int tid = threadIdx.x, wid = tid >> 5, lane = tid & 31;

    // supertile raster (8 m-tiles per group) for L2 reuse
    int tn = N / BN;
    int per = 8 * tn, grp = blockIdx.x / per, rr = blockIdx.x % per;
    int m0 = (grp * 8 + (rr % 8)) * BM;
    int n0 = (rr / 8) * BN;

    const __half* Ab = A  + (size_t)m0 * K;
    const __half* Bb = Bw + (size_t)n0 * K;

    // cp.async offsets: A 4 chunks/thread, B 4 chunks/thread (16B chunks)
    uint32_t sAo[4], gAo[4];
    #pragma unroll
    for (int j = 0; j < 4; j++) {
        int idx = tid + j * NT, r = idx >> 3, c = idx & 7;
        sAo[j] = swz(r, c); gAo[j] = (uint32_t)(r * K + c * 8);
    }

    // warp layout: 2 (m) x 4 (n); warp tile 64x32
    int wm = (wid & 1) * 64, wn = (wid >> 1) * 32;
    int rA128[4], rA7[4], rB128[2], rB7[2];
    int cA = lane >> 4;           // 0..1
    int cB = (lane >> 3) & 1;     // 0..1
    #pragma unroll
    for (int i = 0; i < 4; i++) {
        int ra = wm + i * 16 + (lane & 15);
        rA128[i] = ra * 128; rA7[i] = ra & 7;
    }
    #pragma unroll
    for (int p = 0; p < 2; p++) {
        int rb = wn + p * 16 + (lane & 7) + ((lane >> 4) << 3);
        rB128[p] = rb * 128; rB7[p] = rb & 7;
    }

    float acc[4][4][4];
    #pragma unroll
    for (int i = 0; i < 4; i++)
        #pragma unroll
        for (int j = 0; j < 4; j++)
            #pragma unroll
            for (int q = 0; q < 4; q++) acc[i][j][q] = 0.f;

    const int NK = K / BK;

    #pragma unroll
    for (int s = 0; s < STAGES - 1; s++) {
        uint32_t sA = su + s * STG, sB = sA + ASTG;
        int k0 = s * BK;
        #pragma unroll
        for (int j = 0; j < 4; j++) {
            cp_async16(sA + sAo[j], Ab + gAo[j] + k0);
            cp_async16(sB + sAo[j], Bb + gAo[j] + k0);
        }
        cp_commit();
    }

    int cs = 0, ls = STAGES - 1;
    for (int kt = 0; kt < NK; kt++) {
        asm volatile("cp.async.wait_group %0;" :: "n"(STAGES - 2) : "memory");
        __syncthreads();

        int lt = kt + STAGES - 1;
        if (lt < NK) {
            uint32_t sA = su + ls * STG, sB = sA + ASTG;
            int k0 = lt * BK;
            #pragma unroll
            for (int j = 0; j < 4; j++) {
                cp_async16(sA + sAo[j], Ab + gAo[j] + k0);
                cp_async16(sB + sAo[j], Bb + gAo[j] + k0);
            }
        }
        cp_commit();
        if (++ls == STAGES) ls = 0;

        uint32_t sA = su + cs * STG, sB = sA + ASTG;
        if (++cs == STAGES) cs = 0;
        #pragma unroll
        for (int kk = 0; kk < 4; kk++) {
            uint32_t a[4][4], b[2][4];
            #pragma unroll
            for (int i = 0; i < 4; i++)
                ldsm4(a[i], sA + rA128[i] + (((kk * 2 + cA) ^ rA7[i]) << 4));
            #pragma unroll
            for (int p = 0; p < 2; p++)
                ldsm4(b[p], sB + rB128[p] + (((kk * 2 + cB) ^ rB7[p]) << 4));
            #pragma unroll
            for (int p = 0; p < 2; p++)
                #pragma unroll
                for (int i = 0; i < 4; i++) {
                    mma_f16(acc[i][2*p],     a[i], b[p]);
                    mma_f16(acc[i][2*p + 1], a[i], b[p] + 2);
                }
        }
    }

    // ---- fused epilogue ----
    #pragma unroll
    for (int i = 0; i < 4; i++) {
        int r0 = m0 + wm + i * 16 + (lane >> 2);
        #pragma unroll
        for (int j = 0; j < 4; j++) {
            int c0 = n0 + wn + j * 8 + (lane & 3) * 2;
            float b0 = bias[c0], b1 = bias[c0 + 1];
            #pragma unroll
            for (int h = 0; h < 2; h++) {
                int r = r0 + h * 8;
                float v0 = acc[i][j][2*h]     + b0;
                float v1 = acc[i][j][2*h + 1] + b1;
                if (ACT == 4) {
                    size_t idx = (size_t)r * N + c0;
                    float2 au = *reinterpret_cast<const float2*>(&aux[idx]);
                    *reinterpret_cast<float2*>(&C[idx]) = make_float2(v0 + au.x, v1 + au.y);
                } else if (ACT == 5) {
                    if (c0 < 1024) {
                        *reinterpret_cast<float2*>(&C[(size_t)r * DD + c0]) =
                            make_float2(sigmoidf_(v0), sigmoidf_(v1));
                    } else if (c0 < 3072) {
                        C1h[(size_t)r * DD + ((c0 - 1024) >> 1)] =
                            __float2half_rn(tanhf(v0) * sigmoidf_(v1));
                    } else {
                        *reinterpret_cast<__half2*>(&C2h[(size_t)r * DD + (c0 - 3072)]) =
                            __floats2half2_rn(sigmoidf_(v0), sigmoidf_(v1));
                    }
                } else if (ACT == 6) {
                    Ch[(size_t)r * DFF_ + (c0 >> 1)] =
                        __float2half_rn(v0 * (v1 * sigmoidf_(v1)));
                }
            }
        }
    }
}

// ---------------- chunked linear-recurrence scan ----------------
// NCH=128 chunks of 32 steps: 262144 threads in pass1 for memory-level parallelism
__global__ void scan_pass1(const float* __restrict__ aG, const __half* __restrict__ bVh,
                           float* __restrict__ Pb, float* __restrict__ Hb)
{
    int g = blockIdx.x * blockDim.x + threadIdx.x;    // BB*NCH*DD/2 threads
    int d2 = g & (DD/2 - 1);
    int c  = (g >> 9) & (NCH - 1);
    int b  = g >> 16;
    size_t base = ((size_t)b * LL + (size_t)c * CHUNK) * DD + d2 * 2;
    float2 P = make_float2(1.f, 1.f), hh = make_float2(0.f, 0.f);
    #pragma unroll 4
    for (int t = 0; t < CHUNK; t++) {
        size_t idx = base + (size_t)t * DD;
        float2 a  = *reinterpret_cast<const float2*>(aG + idx);
        float2 bv = __half22float2(*reinterpret_cast<const __half2*>(bVh + idx));
        P.x *= a.x; P.y *= a.y;
        hh.x = fmaf(a.x, hh.x, bv.x);
        hh.y = fmaf(a.y, hh.y, bv.y);
    }
    *reinterpret_cast<float2*>(Pb + (size_t)g * 2) = P;
    *reinterpret_cast<float2*>(Hb + (size_t)g * 2) = hh;
}

// pass2: parallel Kogge-Stone scan over the 128 chunks.
// One 128-thread block per (b,d): thread c holds chunk c's (P,H).
// combine (P1,H1)∘(P2,H2) = (P1*P2, H1*P2 + H2); Ib = exclusive ∘ h0.
__global__ __launch_bounds__(128) void scan_pass2(
    const float* __restrict__ Pb, const float* __restrict__ Hb,
    const float* __restrict__ h0, float* __restrict__ Ib)
{
    int bd = blockIdx.x;            // 0..BB*DD-1
    int b = bd >> 10, d = bd & (DD - 1);
    int c = threadIdx.x;            // chunk 0..127
    int lane = c & 31, w = c >> 5;

    size_t j = ((size_t)(b * NCH + c)) * DD + d;
    float P = Pb[j], H = Hb[j];

    // warp-inclusive scan
    #pragma unroll
    for (int s = 1; s < 32; s <<= 1) {
        float Po = __shfl_up_sync(0xffffffffu, P, s);
        float Ho = __shfl_up_sync(0xffffffffu, H, s);
        if (lane >= s) { H = fmaf(Ho, P, H); P = Po * P; }
    }

    // cross-warp prefix
    __shared__ float wp[4], wh[4];
    if (lane == 31) { wp[w] = P; wh[w] = H; }
    __syncthreads();
    float Pp = 1.f, Hp = 0.f;
    #pragma unroll
    for (int i = 0; i < 3; i++)
        if (i < w) { Hp = fmaf(Hp, wp[i], wh[i]); Pp *= wp[i]; }

    // exclusive within warp
    float Pe = __shfl_up_sync(0xffffffffu, P, 1);
    float He = __shfl_up_sync(0xffffffffu, H, 1);
    if (lane == 0) { Pe = 1.f; He = 0.f; }

    // total exclusive = warp-prefix ∘ warp-exclusive
    float Pt = Pp * Pe;
    float Ht = fmaf(Hp, Pe, He);
    Ib[j] = fmaf(Pt, h0[d], Ht);
}

// pass3 fused with RMSNorm2: one block (512 threads) owns a full D=1024 row
// for one (b, chunk). Writes x1 (fp32) AND xn2 (fp16, normalized) directly.
__global__ __launch_bounds__(512) void scan_pass3n(
    const float* __restrict__ aG, const __half* __restrict__ bVh,
    const __half* __restrict__ oSh, const float* __restrict__ x,
    const float* __restrict__ Ib, const float* __restrict__ w2,
    float* __restrict__ x1, __half* __restrict__ xn2)
{
    int b = blockIdx.x >> 7;            // 4 batches
    int c = blockIdx.x & 127;           // 128 chunks
    int tid = threadIdx.x;              // 512 threads, 2 d's each
    int d0 = tid * 2;

    __shared__ float red[16];
    __shared__ float s_scale;

    size_t base = ((size_t)b * LL + (size_t)c * CHUNK) * DD + d0;
    float2 hh = *reinterpret_cast<const float2*>(Ib + ((size_t)(b * NCH + c) * DD + d0));
    float2 w  = *reinterpret_cast<const float2*>(w2 + d0);

    for (int t = 0; t < CHUNK; t++) {
        size_t idx = base + (size_t)t * DD;
        float2 a  = *reinterpret_cast<const float2*>(aG + idx);
        float2 bv = __half22float2(*reinterpret_cast<const __half2*>(bVh + idx));
        float2 os = __half22float2(*reinterpret_cast<const __half2*>(oSh + idx));
        float2 xv = *reinterpret_cast<const float2*>(x + idx);
        hh.x = fmaf(a.x, hh.x, bv.x);
        hh.y = fmaf(a.y, hh.y, bv.y);
        float y0 = tanhf(hh.x) * os.x + xv.x;
        float y1 = tanhf(hh.y) * os.y + xv.y;
        *reinterpret_cast<float2*>(x1 + idx) = make_float2(y0, y1);

        // block-reduce sum of squares over D=1024 (512 threads x 2)
        float ss = y0 * y0 + y1 * y1;
        #pragma unroll
        for (int of = 16; of > 0; of >>= 1) ss += __shfl_xor_sync(0xffffffffu, ss, of);
        if ((tid & 31) == 0) red[tid >> 5] = ss;
        __syncthreads();
        if (tid < 32) {
            float v = (tid < 16) ? red[tid] : 0.f;
            #pragma unroll
            for (int of = 8; of > 0; of >>= 1) v += __shfl_xor_sync(0xffffffffu, v, of);
            if (tid == 0) s_scale = rsqrtf(v / (float)DD + 1e-6f);
        }
        __syncthreads();
        float s = s_scale;
        *reinterpret_cast<__half2*>(xn2 + idx) =
            __floats2half2_rn(y0 * s * w.x, y1 * s * w.y);
        __syncthreads();   // protect s_scale for next t
    }
}

// ---------------- launcher ----------------
extern "C" void kernel_launch(void* const* d_in, const int* in_sizes, int n_in,
                              void* d_out, int out_size)
{
    (void)in_sizes; (void)n_in; (void)out_size;
    const float* x   = (const float*)d_in[0];
    const float* wf  = (const float*)d_in[1];
    const float* bf_ = (const float*)d_in[2];
    const float* wi  = (const float*)d_in[3];
    const float* bi_ = (const float*)d_in[4];
    const float* wg  = (const float*)d_in[5];
    const float* bg_ = (const float*)d_in[6];
    const float* wo  = (const float*)d_in[7];
    const float* bo_ = (const float*)d_in[8];
    const float* h0  = (const float*)d_in[9];
    const float* n1w = (const float*)d_in[10];
    const float* n2w = (const float*)d_in[11];
    const float* wfc = (const float*)d_in[12];
    const float* bfc = (const float*)d_in[13];
    const float* wfa = (const float*)d_in[14];
    const float* bfa = (const float*)d_in[15];
    const float* wou = (const float*)d_in[16];
    const float* bou = (const float*)d_in[17];
    float* out = (float*)d_out;

    float *ga, *x1, *P, *H, *I, *bg4, *bff;
    cudaGetSymbolAddress((void**)&ga,  g_a);
    cudaGetSymbolAddress((void**)&x1,  g_x1);
    cudaGetSymbolAddress((void**)&P,   g_P);
    cudaGetSymbolAddress((void**)&H,   g_H);
    cudaGetSymbolAddress((void**)&I,   g_I);
    cudaGetSymbolAddress((void**)&bg4, g_bg);
    cudaGetSymbolAddress((void**)&bff, g_bff);

    __half *gbvh, *goh, *xn, *xn2, *hff, *wgt, *wff, *wout_;
    cudaGetSymbolAddress((void**)&gbvh, g_bvh);
    cudaGetSymbolAddress((void**)&goh,  g_oh);
    cudaGetSymbolAddress((void**)&xn,   g_xn);
    cudaGetSymbolAddress((void**)&xn2,  g_xn2);
    cudaGetSymbolAddress((void**)&hff,  g_hff);
    cudaGetSymbolAddress((void**)&wgt,  g_wgt);
    cudaGetSymbolAddress((void**)&wff,  g_wff);
    cudaGetSymbolAddress((void**)&wout_,g_wout);

    cudaFuncSetAttribute(tc_gemm<4>, cudaFuncAttributeMaxDynamicSharedMemorySize, GSMEM);
    cudaFuncSetAttribute(tc_gemm<5>, cudaFuncAttributeMaxDynamicSharedMemorySize, GSMEM);
    cudaFuncSetAttribute(tc_gemm<6>, cudaFuncAttributeMaxDynamicSharedMemorySize, GSMEM);

    // 0) fused weight/bias packing + RMSNorm1 (single launch, overlapped)
    pack_norm<<<PACK_BLKS + MM, 256>>>(wf, wi, wg, wo, wfc, wfa, wou,
                                       bf_, bi_, bg_, bo_, bfc, bfa,
                                       x, n1w,
                                       wgt, wff, wout_, bg4, bff, xn);

    // 1) gate GEMM (N=4096) -> a (fp32), bv (fp16), o (fp16)
    int gGates = (MM/BM) * ((4*DD)/BN);
    tc_gemm<5><<<gGates, NT, GSMEM>>>(xn, wgt, bg4, nullptr, ga, nullptr, gbvh, goh,
                                      MM, 4*DD, DD);

    // 2) scan + output gate + residual + fused RMSNorm2 -> x1 (fp32), xn2 (fp16)
    scan_pass1<<<(BB*NCH*DD/2)/256, 256>>>(ga, gbvh, P, H);
    scan_pass2<<<BB*DD, 128>>>(P, H, h0, I);
    scan_pass3n<<<BB*NCH, 512>>>(ga, gbvh, goh, x, I, n2w, x1, xn2);

    // 3) fused FFN-up (N=8192, interleaved) -> hff fp16
    int gFF = (MM/BM) * ((2*DFF_)/BN);
    tc_gemm<6><<<gFF, NT, GSMEM>>>(xn2, wff, bff, nullptr, nullptr, hff, nullptr, nullptr,
                                   MM, 2*DFF_, DD);

    // 4) down-proj + b_out + x1 -> d_out
    int gOut = (MM/BM) * (DD/BN);
    tc_gemm<4><<<gOut, NT, GSMEM>>>(hff, wout_, bou, x1, out, nullptr, nullptr, nullptr,
                                    MM, DD, DFF_);
}